// round 13
// baseline (speedup 1.0000x reference)
#include <cuda_runtime.h>
#include <cuda_bf16.h>
#include <cuda_fp16.h>
#include <cstdint>

// ---------------------------------------------------------------------------
// MultiHeadAttention: out = softmax((XQ Wq^T)(XK Wk^T)^T * 64) (XV Wv^T)
// b=2, s=2048, d=1024, heads=16, hd=64.
// Round 11: single __syncthreads per pipeline iteration in BOTH mainloops
// (fill issued after the barrier; ring safety: fill(next) writes a stage
// whose readers finished before that barrier). Attention: 3-stage ring,
// depth-2 prefetch. Arithmetic unchanged from R10.
// ---------------------------------------------------------------------------

#define BATCH     2
#define SEQ       2048
#define DMODEL    1024
#define NHEADS    16
#define HDIM      64

// bf16x2 split of raw inputs/weights
__device__ __nv_bfloat16 g_Xhi[3ull * 4096 * 1024];
__device__ __nv_bfloat16 g_Xlo[3ull * 4096 * 1024];
__device__ __nv_bfloat16 g_Whi[3ull * 1024 * 1024];
__device__ __nv_bfloat16 g_Wlo[3ull * 1024 * 1024];
// Projected Q/K head-split [b][h][s][hd], bf16 hi/lo; V as plain fp16
__device__ __nv_bfloat16 g_Qhi[BATCH * NHEADS * SEQ * HDIM];
__device__ __nv_bfloat16 g_Qlo[BATCH * NHEADS * SEQ * HDIM];
__device__ __nv_bfloat16 g_Khi[BATCH * NHEADS * SEQ * HDIM];
__device__ __nv_bfloat16 g_Klo[BATCH * NHEADS * SEQ * HDIM];
__device__ __half        g_Vh [BATCH * NHEADS * SEQ * HDIM];

#define EXP2_SCALE 92.33248261689366f   // 64 * log2(e)

__device__ __forceinline__ uint32_t smem_u32(const void* p) {
    uint32_t a;
    asm("{ .reg .u64 t; cvta.to.shared.u64 t, %1; cvt.u32.u64 %0, t; }"
        : "=r"(a) : "l"(p));
    return a;
}
__device__ __forceinline__ uint32_t sw128(uint32_t b) {
    return b ^ ((b >> 3) & 0x70);
}
__device__ __forceinline__ float ex2f(float x) {
    float y;
    asm("ex2.approx.f32 %0, %1;" : "=f"(y) : "f"(x));
    return y;
}

#define LDSM_X4(r0, r1, r2, r3, addr) \
    asm volatile("ldmatrix.sync.aligned.m8n8.x4.shared.b16 {%0,%1,%2,%3}, [%4];" \
                 : "=r"(r0), "=r"(r1), "=r"(r2), "=r"(r3) : "r"(addr))
#define LDSM_X4_T(r0, r1, r2, r3, addr) \
    asm volatile("ldmatrix.sync.aligned.m8n8.x4.trans.shared.b16 {%0,%1,%2,%3}, [%4];" \
                 : "=r"(r0), "=r"(r1), "=r"(r2), "=r"(r3) : "r"(addr))

#define MMA_BF16(d, a, b0, b1) \
    asm volatile("mma.sync.aligned.m16n8k16.row.col.f32.bf16.bf16.f32 " \
                 "{%0,%1,%2,%3}, {%4,%5,%6,%7}, {%8,%9}, {%0,%1,%2,%3};" \
                 : "+f"((d)[0]), "+f"((d)[1]), "+f"((d)[2]), "+f"((d)[3]) \
                 : "r"((a)[0]), "r"((a)[1]), "r"((a)[2]), "r"((a)[3]), \
                   "r"(b0), "r"(b1))
#define MMA_F16(d, a, b0, b1) \
    asm volatile("mma.sync.aligned.m16n8k16.row.col.f32.f16.f16.f32 " \
                 "{%0,%1,%2,%3}, {%4,%5,%6,%7}, {%8,%9}, {%0,%1,%2,%3};" \
                 : "+f"((d)[0]), "+f"((d)[1]), "+f"((d)[2]), "+f"((d)[3]) \
                 : "r"((a)[0]), "r"((a)[1]), "r"((a)[2]), "r"((a)[3]), \
                   "r"(b0), "r"(b1))

#define CP_A16(dst, src) \
    asm volatile("cp.async.cg.shared.global [%0], [%1], 16;" \
                 :: "r"(dst), "l"(src) : "memory")
#define CP_COMMIT() asm volatile("cp.async.commit_group;" ::: "memory")
#define CP_WAIT(n)  asm volatile("cp.async.wait_group %0;" :: "n"(n) : "memory")

__device__ __forceinline__ uint32_t pack_bf16(float lo, float hi) {
    uint32_t u = (uint32_t)__bfloat16_as_ushort(__float2bfloat16(lo)) |
                 ((uint32_t)__bfloat16_as_ushort(__float2bfloat16(hi)) << 16);
    return u;
}

// ===========================================================================
// Fused split kernel (proven R9): all six tensors -> bf16 hi/lo, one launch.
// ===========================================================================
#define XN4 1048576
#define WN4 262144
#define SPLIT_TOTAL (3 * XN4 + 3 * WN4)

__global__ __launch_bounds__(256)
void split_all_kernel(const float4* __restrict__ q, const float4* __restrict__ k,
                      const float4* __restrict__ v, const float4* __restrict__ Wq,
                      const float4* __restrict__ Wk, const float4* __restrict__ Wv,
                      __nv_bfloat16* __restrict__ Xhi, __nv_bfloat16* __restrict__ Xlo,
                      __nv_bfloat16* __restrict__ Whi, __nv_bfloat16* __restrict__ Wlo)
{
    int i = blockIdx.x * 256 + threadIdx.x;
    if (i >= SPLIT_TOTAL) return;

    const float4* src;
    __nv_bfloat16 *hi, *lo;
    int idx;
    if (i < 3 * XN4) {
        int r = i / XN4;
        idx = i - r * XN4;
        src = (r == 0) ? q : (r == 1) ? k : v;
        hi = Xhi + (size_t)r * 4194304;
        lo = Xlo + (size_t)r * 4194304;
    } else {
        int j = i - 3 * XN4;
        int r = j / WN4;
        idx = j - r * WN4;
        src = (r == 0) ? Wq : (r == 1) ? Wk : Wv;
        hi = Whi + (size_t)r * 1048576;
        lo = Wlo + (size_t)r * 1048576;
    }

    float4 val = src[idx];
    float xs[4] = {val.x, val.y, val.z, val.w};
    uint32_t hb[4], lb[4];
#pragma unroll
    for (int j = 0; j < 4; j++) {
        __nv_bfloat16 h = __float2bfloat16(xs[j]);
        __nv_bfloat16 l = __float2bfloat16(xs[j] - __bfloat162float(h));
        hb[j] = (uint32_t)__bfloat16_as_ushort(h);
        lb[j] = (uint32_t)__bfloat16_as_ushort(l);
    }
    uint2 hp, lp;
    hp.x = hb[0] | (hb[1] << 16); hp.y = hb[2] | (hb[3] << 16);
    lp.x = lb[0] | (lb[1] << 16); lp.y = lb[2] | (lb[3] << 16);
    reinterpret_cast<uint2*>(hi)[idx] = hp;
    reinterpret_cast<uint2*>(lo)[idx] = lp;
}

// ===========================================================================
// Projection GEMM: 512 threads, CTA tile 256x128, 16 warps (8m x 2n),
// warp tile 32x64. K-chunk 64, SW128, cp.async 2-stage.
// Round 11: single __syncthreads per chunk; fill issued AFTER the barrier.
// Stage = Ahi(32K)|Alo(32K)|Bhi(16K)|Blo(16K) = 96KB; 2 stages = 192KB.
// z==2 (V) epilogue emits plain fp16.
// ===========================================================================
#define PROJ_STAGE  98304
#define PROJ_SMEM   (2 * PROJ_STAGE)
#define PROJ_NCHUNK (DMODEL / 64)   // 16

__global__ __launch_bounds__(512)
void proj_mma_kernel(const __nv_bfloat16* __restrict__ Xhi_all,
                     const __nv_bfloat16* __restrict__ Xlo_all,
                     const __nv_bfloat16* __restrict__ Whi_all,
                     const __nv_bfloat16* __restrict__ Wlo_all,
                     __nv_bfloat16* __restrict__ Qhi, __nv_bfloat16* __restrict__ Qlo,
                     __nv_bfloat16* __restrict__ Khi, __nv_bfloat16* __restrict__ Klo,
                     __half* __restrict__ Vh)
{
    extern __shared__ char smp[];
    const uint32_t sm0 = smem_u32(smp);

    const int tid  = threadIdx.x;
    const int wid  = tid >> 5, lane = tid & 31;
    const int wm   = wid >> 1;           // 0..7 -> m offset wm*32
    const int wn   = wid & 1;            // 0..1 -> n offset wn*64
    const int m0   = blockIdx.x * 256;
    const int n0   = blockIdx.y * 128;
    const int z    = blockIdx.z;

    const uint4* gAh = (const uint4*)(Xhi_all + (size_t)z * 4096 * 1024 + (size_t)m0 * 1024);
    const uint4* gAl = (const uint4*)(Xlo_all + (size_t)z * 4096 * 1024 + (size_t)m0 * 1024);
    const uint4* gBh = (const uint4*)(Whi_all + (size_t)z * 1024 * 1024 + (size_t)n0 * 1024);
    const uint4* gBl = (const uint4*)(Wlo_all + (size_t)z * 1024 * 1024 + (size_t)n0 * 1024);

    // Fill stage (c&1) with chunk c: Ahi 256x64 | Alo | Bhi 128x64 | Blo
    auto fill = [&](int c) {
        uint32_t sb = sm0 + (c & 1) * PROJ_STAGE;
#pragma unroll
        for (int i = 0; i < 12; i++) {
            int lin = tid + i * 512;
            int region = lin >> 11;          // 0:Ahi 1:Alo 2:B
            int rem = lin & 2047;
            const uint4* src;
            uint32_t dst;
            if (region < 2) {
                int row = rem >> 3, col = rem & 7;   // row 0..255
                src = (region == 0 ? gAh : gAl) + (size_t)row * 128 + c * 8 + col;
                dst = sb + region * 32768 + sw128(row * 128 + col * 16);
            } else {
                int sub = rem >> 10;                  // 0:Bhi 1:Blo
                int r2  = rem & 1023;
                int row = r2 >> 3, col = r2 & 7;      // row 0..127
                src = (sub == 0 ? gBh : gBl) + (size_t)row * 128 + c * 8 + col;
                dst = sb + 65536 + sub * 16384 + sw128(row * 128 + col * 16);
            }
            CP_A16(dst, src);
        }
    };

    float acc[2][8][4];
#pragma unroll
    for (int i = 0; i < 2; i++)
#pragma unroll
        for (int j = 0; j < 8; j++)
#pragma unroll
            for (int e = 0; e < 4; e++) acc[i][j][e] = 0.f;

    const int rIn    = lane & 7;
    const int a_rsel = ((lane >> 3) & 1) * 8;
    const int a_ksel = ((lane >> 4) & 1) * 16;
    const int b_nsel = ((lane >> 4) & 1) * 8;
    const int b_ksel = ((lane >> 3) & 1) * 16;

    fill(0);
    CP_COMMIT();

    for (int c = 0; c < PROJ_NCHUNK; c++) {
        // Only fill(c) can be pending here (fill(c+1) is issued below).
        CP_WAIT(0);
        __syncthreads();   // single barrier: data visible AND prior stage reads done
        if (c + 1 < PROJ_NCHUNK) {
            fill(c + 1);   // writes stage (c+1)&1: its readers finished before the sync
            CP_COMMIT();
        }

        const uint32_t st = sm0 + (c & 1) * PROJ_STAGE;
        const uint32_t ah_u = st, al_u = st + 32768;
        const uint32_t bh_u = st + 65536, bl_u = st + 81920;

#pragma unroll
        for (int ks = 0; ks < 4; ks++) {
            uint32_t ah[2][4], al[2][4];
#pragma unroll
            for (int mi = 0; mi < 2; mi++) {
                int row = wm * 32 + mi * 16 + a_rsel + rIn;
                uint32_t off = sw128(row * 128 + ks * 32 + a_ksel);
                LDSM_X4(ah[mi][0], ah[mi][1], ah[mi][2], ah[mi][3], ah_u + off);
                LDSM_X4(al[mi][0], al[mi][1], al[mi][2], al[mi][3], al_u + off);
            }
#pragma unroll
            for (int njp = 0; njp < 4; njp++) {
                int nrow = wn * 64 + njp * 16 + b_nsel + rIn;
                uint32_t off = sw128(nrow * 128 + ks * 32 + b_ksel);
                uint32_t bhf[4], blf[4];
                LDSM_X4(bhf[0], bhf[1], bhf[2], bhf[3], bh_u + off);
                LDSM_X4(blf[0], blf[1], blf[2], blf[3], bl_u + off);
#pragma unroll
                for (int mi = 0; mi < 2; mi++) {
                    MMA_BF16(acc[mi][njp * 2],     ah[mi], bhf[0], bhf[1]);
                    MMA_BF16(acc[mi][njp * 2],     al[mi], bhf[0], bhf[1]);
                    MMA_BF16(acc[mi][njp * 2],     ah[mi], blf[0], blf[1]);
                    MMA_BF16(acc[mi][njp * 2 + 1], ah[mi], bhf[2], bhf[3]);
                    MMA_BF16(acc[mi][njp * 2 + 1], al[mi], bhf[2], bhf[3]);
                    MMA_BF16(acc[mi][njp * 2 + 1], ah[mi], blf[2], blf[3]);
                }
            }
        }
        // no end-of-chunk barrier: next iteration's sync precedes the next fill
    }

    // Epilogue: head-split [b][h][s][hd]; Q/K -> bf16 hi/lo, V -> fp16
    const int rr = lane >> 2;
    const int cc = (lane & 3) * 2;
    __nv_bfloat16* OutHi = (z == 0) ? Qhi : Khi;
    __nv_bfloat16* OutLo = (z == 0) ? Qlo : Klo;
#pragma unroll
    for (int mi = 0; mi < 2; mi++) {
#pragma unroll
        for (int nj = 0; nj < 8; nj++) {
            int n  = n0 + wn * 64 + nj * 8 + cc;
            int h  = n >> 6, hd = n & 63;
            int m  = m0 + wm * 32 + mi * 16 + rr;
            int bb = m >> 11, ss = m & 2047;
            size_t idx0 = (((size_t)(bb * NHEADS + h)) * SEQ + ss) * HDIM + hd;
#pragma unroll
            for (int half_i = 0; half_i < 2; half_i++) {   // rows m, m+8
                float v0 = acc[mi][nj][half_i * 2 + 0];
                float v1 = acc[mi][nj][half_i * 2 + 1];
                size_t idx = idx0 + (size_t)half_i * 8 * HDIM;
                if (z == 2) {
                    __half2 hv = __floats2half2_rn(v0, v1);
                    *reinterpret_cast<__half2*>(Vh + idx) = hv;
                } else {
                    __nv_bfloat16 h0 = __float2bfloat16(v0);
                    __nv_bfloat16 h1 = __float2bfloat16(v1);
                    uint32_t uhi = (uint32_t)__bfloat16_as_ushort(h0) |
                                   ((uint32_t)__bfloat16_as_ushort(h1) << 16);
                    uint32_t ulo = pack_bf16(v0 - __bfloat162float(h0),
                                             v1 - __bfloat162float(h1));
                    *reinterpret_cast<uint32_t*>(OutHi + idx) = uhi;
                    *reinterpret_cast<uint32_t*>(OutLo + idx) = ulo;
                }
            }
        }
    }
}

// ===========================================================================
// Tensor-core flash attention. Round 11: 3-stage KV ring, depth-2 prefetch,
// single __syncthreads per tile (fill issued AFTER the barrier).
// SMEM: Q 32KB | 3 x 24KB = 104KB -> 2 CTAs/SM.
// ===========================================================================
#define AT_STAGE 24576
#define AT_SMEM  (32768 + 3 * AT_STAGE)
#define NT       (SEQ / 64)

__global__ __launch_bounds__(256)
void attn_tc_kernel(const __nv_bfloat16* __restrict__ Qhi,
                    const __nv_bfloat16* __restrict__ Qlo,
                    const __nv_bfloat16* __restrict__ Khi,
                    const __nv_bfloat16* __restrict__ Klo,
                    const __half* __restrict__ Vh,
                    float* __restrict__ Out)
{
    extern __shared__ char sma[];
    const uint32_t sm0 = smem_u32(sma);
    const int tid  = threadIdx.x;
    const int lane = tid & 31;
    const int wq   = tid >> 5;
    const int q0   = blockIdx.x * 128;
    const int h    = blockIdx.y;
    const int b    = blockIdx.z;
    const size_t base = ((size_t)(b * NHEADS + h)) * SEQ * HDIM;

    const uint4* gqh = (const uint4*)(Qhi + base + (size_t)q0 * HDIM);
    const uint4* gql = (const uint4*)(Qlo + base + (size_t)q0 * HDIM);
    const uint4* gkh = (const uint4*)(Khi + base);
    const uint4* gkl = (const uint4*)(Klo + base);
    const uint4* gvh = (const uint4*)(Vh  + base);

    // K hi (8K) + K lo (8K) + V fp16 (8K) per stage; ring of 3
    auto kv_fill = [&](int t) {
        uint32_t dstbase = sm0 + 32768 + (t % 3) * AT_STAGE;
        int kt = t * 64;
#pragma unroll
        for (int i = 0; i < 6; i++) {
            int lin = tid + i * 256;
            int mat = lin >> 9;                 // 0: Khi, 1: Klo, 2: V
            int rem = lin & 511;
            int row = rem >> 3, col = rem & 7;
            const uint4* src =
                (mat == 0 ? gkh : mat == 1 ? gkl : gvh)
                + (size_t)(kt + row) * 8 + col;
            uint32_t dst = dstbase + mat * 8192 + sw128(row * 128 + col * 16);
            CP_A16(dst, src);
        }
    };
    kv_fill(0);
    CP_COMMIT();
    kv_fill(1);
    CP_COMMIT();

    // ---- load Q tile (128 x 64 bf16, hi+lo) into smem
#pragma unroll
    for (int i = 0; i < 4; i++) {
        int lin = tid + i * 256;
        int row = lin >> 3, col = lin & 7;
        uint32_t off = sw128(row * 128 + col * 16);
        *reinterpret_cast<uint4*>(sma + off)         = gqh[row * 8 + col];
        *reinterpret_cast<uint4*>(sma + 16384 + off) = gql[row * 8 + col];
    }
    __syncthreads();   // Q smem ready

    const int rIn    = lane & 7;
    const int a_rsel = ((lane >> 3) & 1) * 8;
    const int a_ksel = ((lane >> 4) & 1) * 16;
    const int b_nsel = ((lane >> 4) & 1) * 8;
    const int b_ksel = ((lane >> 3) & 1) * 16;
    const int v_rsel = ((lane >> 3) & 1) * 8;
    const int v_nsel = ((lane >> 4) & 1) * 16;

    uint32_t qh[4][4], ql[4][4];
#pragma unroll
    for (int ks = 0; ks < 4; ks++) {
        uint32_t off = sw128((wq * 16 + a_rsel + rIn) * 128 + ks * 32 + a_ksel);
        LDSM_X4(qh[ks][0], qh[ks][1], qh[ks][2], qh[ks][3], sm0 + off);
        LDSM_X4(ql[ks][0], ql[ks][1], ql[ks][2], ql[ks][3], sm0 + 16384 + off);
    }

    float o[8][4];
#pragma unroll
    for (int v = 0; v < 8; v++)
#pragma unroll
        for (int e = 0; e < 4; e++) o[v][e] = 0.f;
    float m0r = -3.0e38f, m1r = -3.0e38f;   // log2-domain running max
    float l0 = 0.f, l1 = 0.f;

    for (int t = 0; t < NT; t++) {
        // groups in flight: fill(t) [maybe], fill(t+1) [if issued].
        // cp.async groups retire in order -> WAIT(1) guarantees fill(t) done
        // whenever fill(t+1) exists; WAIT(0) at the tail.
        if (t + 1 < NT) { CP_WAIT(1); } else { CP_WAIT(0); }
        __syncthreads();   // single barrier per tile
        if (t + 2 < NT) {
            kv_fill(t + 2);   // stage (t+2)%3 == (t-1)%3: readers done pre-sync
            CP_COMMIT();
        }
        const uint32_t kb = sm0 + 32768 + (t % 3) * AT_STAGE;
        const uint32_t vb = kb + 16384;

        // ---- S = Q K^T (3-term bf16 split), raw dot domain
        float s[8][4];
#pragma unroll
        for (int j = 0; j < 8; j++)
#pragma unroll
            for (int e = 0; e < 4; e++) s[j][e] = 0.f;
#pragma unroll
        for (int ks = 0; ks < 4; ks++) {
#pragma unroll
            for (int np = 0; np < 4; np++) {
                uint32_t off = sw128((np * 16 + b_nsel + rIn) * 128 + ks * 32 + b_ksel);
                uint32_t kf[4], lf[4];
                LDSM_X4(kf[0], kf[1], kf[2], kf[3], kb + off);
                LDSM_X4(lf[0], lf[1], lf[2], lf[3], kb + 8192 + off);
                MMA_BF16(s[np * 2],     qh[ks], kf[0], kf[1]);
                MMA_BF16(s[np * 2],     ql[ks], kf[0], kf[1]);
                MMA_BF16(s[np * 2],     qh[ks], lf[0], lf[1]);
                MMA_BF16(s[np * 2 + 1], qh[ks], kf[2], kf[3]);
                MMA_BF16(s[np * 2 + 1], ql[ks], kf[2], kf[3]);
                MMA_BF16(s[np * 2 + 1], qh[ks], lf[2], lf[3]);
            }
        }

        // ---- softmax in exp2 domain: weight = 2^(s*C - M2)
        float mt0 = -3.0e38f, mt1 = -3.0e38f;
#pragma unroll
        for (int j = 0; j < 8; j++) {
            mt0 = fmaxf(mt0, fmaxf(s[j][0], s[j][1]));
            mt1 = fmaxf(mt1, fmaxf(s[j][2], s[j][3]));
        }
        mt0 = fmaxf(mt0, __shfl_xor_sync(0xffffffffu, mt0, 1));
        mt0 = fmaxf(mt0, __shfl_xor_sync(0xffffffffu, mt0, 2));
        mt1 = fmaxf(mt1, __shfl_xor_sync(0xffffffffu, mt1, 1));
        mt1 = fmaxf(mt1, __shfl_xor_sync(0xffffffffu, mt1, 2));
        float M0 = fmaxf(m0r, mt0 * EXP2_SCALE);
        float M1 = fmaxf(m1r, mt1 * EXP2_SCALE);
        float a0 = ex2f(m0r - M0);
        float a1 = ex2f(m1r - M1);
        m0r = M0; m1r = M1;

        float rs0 = 0.f, rs1 = 0.f;
        uint32_t ap[4][4];   // P fragments, fp16
#pragma unroll
        for (int jp = 0; jp < 4; jp++) {
#pragma unroll
            for (int half_i = 0; half_i < 2; half_i++) {
                int j = jp * 2 + half_i;
                float p0 = ex2f(fmaf(s[j][0], EXP2_SCALE, -M0));
                float p1 = ex2f(fmaf(s[j][1], EXP2_SCALE, -M0));
                float p2 = ex2f(fmaf(s[j][2], EXP2_SCALE, -M1));
                float p3 = ex2f(fmaf(s[j][3], EXP2_SCALE, -M1));
                __half2 h01 = __floats2half2_rn(p0, p1);
                __half2 h23 = __floats2half2_rn(p2, p3);
                // l sums the ROUNDED p: quantization cancels in out = (P.V)/l
                float2 f01 = __half22float2(h01);
                float2 f23 = __half22float2(h23);
                rs0 += f01.x + f01.y;
                rs1 += f23.x + f23.y;
                ap[jp][half_i * 2 + 0] = *reinterpret_cast<uint32_t*>(&h01);
                ap[jp][half_i * 2 + 1] = *reinterpret_cast<uint32_t*>(&h23);
            }
        }

        rs0 += __shfl_xor_sync(0xffffffffu, rs0, 1);
        rs0 += __shfl_xor_sync(0xffffffffu, rs0, 2);
        rs1 += __shfl_xor_sync(0xffffffffu, rs1, 1);
        rs1 += __shfl_xor_sync(0xffffffffu, rs1, 2);
        l0 = l0 * a0 + rs0;
        l1 = l1 * a1 + rs1;
#pragma unroll
        for (int v = 0; v < 8; v++) {
            o[v][0] *= a0; o[v][1] *= a0;
            o[v][2] *= a1; o[v][3] *= a1;
        }

        // ---- O += P V (single fp16 term), V via ldmatrix.trans
#pragma unroll
        for (int t4 = 0; t4 < 4; t4++) {
#pragma unroll
            for (int vp = 0; vp < 4; vp++) {
                uint32_t off = sw128((t4 * 16 + v_rsel + rIn) * 128 + vp * 32 + v_nsel);
                uint32_t vf[4];
                LDSM_X4_T(vf[0], vf[1], vf[2], vf[3], vb + off);
                MMA_F16(o[vp * 2],     ap[t4], vf[0], vf[1]);
                MMA_F16(o[vp * 2 + 1], ap[t4], vf[2], vf[3]);
            }
        }
        // no end-of-tile barrier: next tile's sync precedes the next fill
    }

    // ---- epilogue: normalize, write out[b][s][h*64+hd]
    float inv0 = 1.f / l0;
    float inv1 = 1.f / l1;
    int s0 = q0 + wq * 16 + (lane >> 2);
    int hd0 = h * 64 + 2 * (lane & 3);
#pragma unroll
    for (int v = 0; v < 8; v++) {
        float2 w0 = make_float2(o[v][0] * inv0, o[v][1] * inv0);
        float2 w1 = make_float2(o[v][2] * inv1, o[v][3] * inv1);
        *reinterpret_cast<float2*>(
            &Out[(size_t)(b * SEQ + s0) * DMODEL + hd0 + v * 8]) = w0;
        *reinterpret_cast<float2*>(
            &Out[(size_t)(b * SEQ + s0 + 8) * DMODEL + hd0 + v * 8]) = w1;
    }
}

// ---------------------------------------------------------------------------
extern "C" void kernel_launch(void* const* d_in, const int* in_sizes, int n_in,
                              void* d_out, int out_size)
{
    const float* q  = (const float*)d_in[0];
    const float* k  = (const float*)d_in[1];
    const float* v  = (const float*)d_in[2];
    const float* Wq = (const float*)d_in[3];
    const float* Wk = (const float*)d_in[4];
    const float* Wv = (const float*)d_in[5];
    float* out = (float*)d_out;

    __nv_bfloat16 *Xhi, *Xlo, *Whi, *Wlo;
    __nv_bfloat16 *Qhi, *Qlo, *Khi, *Klo;
    __half *Vh;
    cudaGetSymbolAddress((void**)&Xhi, g_Xhi);
    cudaGetSymbolAddress((void**)&Xlo, g_Xlo);
    cudaGetSymbolAddress((void**)&Whi, g_Whi);
    cudaGetSymbolAddress((void**)&Wlo, g_Wlo);
    cudaGetSymbolAddress((void**)&Qhi, g_Qhi);
    cudaGetSymbolAddress((void**)&Qlo, g_Qlo);
    cudaGetSymbolAddress((void**)&Khi, g_Khi);
    cudaGetSymbolAddress((void**)&Klo, g_Klo);
    cudaGetSymbolAddress((void**)&Vh,  g_Vh);

    cudaFuncSetAttribute(proj_mma_kernel,
                         cudaFuncAttributeMaxDynamicSharedMemorySize, PROJ_SMEM);
    cudaFuncSetAttribute(attn_tc_kernel,
                         cudaFuncAttributeMaxDynamicSharedMemorySize, AT_SMEM);

    split_all_kernel<<<(SPLIT_TOTAL + 255) / 256, 256>>>(
        (const float4*)q, (const float4*)k, (const float4*)v,
        (const float4*)Wq, (const float4*)Wk, (const float4*)Wv,
        Xhi, Xlo, Whi, Wlo);

    dim3 pg(4096 / 256, 1024 / 128, 3);   // (16, 8, 3)
    proj_mma_kernel<<<pg, 512, PROJ_SMEM>>>(Xhi, Xlo, Whi, Wlo,
                                            Qhi, Qlo, Khi, Klo, Vh);

    dim3 ag(SEQ / 128, NHEADS, BATCH);    // (16, 16, 2)
    attn_tc_kernel<<<ag, 256, AT_SMEM>>>(Qhi, Qlo, Khi, Klo, Vh, out);
}

// round 14
// speedup vs baseline: 1.0237x; 1.0237x over previous
#include <cuda_runtime.h>
#include <cuda_bf16.h>
#include <cuda_fp16.h>
#include <cstdint>

// ---------------------------------------------------------------------------
// MultiHeadAttention: out = softmax((XQ Wq^T)(XK Wk^T)^T * 64) (XV Wv^T)
// b=2, s=2048, d=1024, heads=16, hd=64.
// Round 12: attention warps widened to 32 q-rows (4 warps/CTA, 128 threads).
// Each warp reads K/V tiles once -> smem LDSM traffic per tile halves
// (the measured bottleneck). Proj + split unchanged from the 429us config.
// ---------------------------------------------------------------------------

#define BATCH     2
#define SEQ       2048
#define DMODEL    1024
#define NHEADS    16
#define HDIM      64

// bf16x2 split of raw inputs/weights
__device__ __nv_bfloat16 g_Xhi[3ull * 4096 * 1024];
__device__ __nv_bfloat16 g_Xlo[3ull * 4096 * 1024];
__device__ __nv_bfloat16 g_Whi[3ull * 1024 * 1024];
__device__ __nv_bfloat16 g_Wlo[3ull * 1024 * 1024];
// Projected Q/K head-split [b][h][s][hd], bf16 hi/lo; V as plain fp16
__device__ __nv_bfloat16 g_Qhi[BATCH * NHEADS * SEQ * HDIM];
__device__ __nv_bfloat16 g_Qlo[BATCH * NHEADS * SEQ * HDIM];
__device__ __nv_bfloat16 g_Khi[BATCH * NHEADS * SEQ * HDIM];
__device__ __nv_bfloat16 g_Klo[BATCH * NHEADS * SEQ * HDIM];
__device__ __half        g_Vh [BATCH * NHEADS * SEQ * HDIM];

#define EXP2_SCALE 92.33248261689366f   // 64 * log2(e)

__device__ __forceinline__ uint32_t smem_u32(const void* p) {
    uint32_t a;
    asm("{ .reg .u64 t; cvta.to.shared.u64 t, %1; cvt.u32.u64 %0, t; }"
        : "=r"(a) : "l"(p));
    return a;
}
__device__ __forceinline__ uint32_t sw128(uint32_t b) {
    return b ^ ((b >> 3) & 0x70);
}
__device__ __forceinline__ float ex2f(float x) {
    float y;
    asm("ex2.approx.f32 %0, %1;" : "=f"(y) : "f"(x));
    return y;
}

#define LDSM_X4(r0, r1, r2, r3, addr) \
    asm volatile("ldmatrix.sync.aligned.m8n8.x4.shared.b16 {%0,%1,%2,%3}, [%4];" \
                 : "=r"(r0), "=r"(r1), "=r"(r2), "=r"(r3) : "r"(addr))
#define LDSM_X4_T(r0, r1, r2, r3, addr) \
    asm volatile("ldmatrix.sync.aligned.m8n8.x4.trans.shared.b16 {%0,%1,%2,%3}, [%4];" \
                 : "=r"(r0), "=r"(r1), "=r"(r2), "=r"(r3) : "r"(addr))

#define MMA_BF16(d, a, b0, b1) \
    asm volatile("mma.sync.aligned.m16n8k16.row.col.f32.bf16.bf16.f32 " \
                 "{%0,%1,%2,%3}, {%4,%5,%6,%7}, {%8,%9}, {%0,%1,%2,%3};" \
                 : "+f"((d)[0]), "+f"((d)[1]), "+f"((d)[2]), "+f"((d)[3]) \
                 : "r"((a)[0]), "r"((a)[1]), "r"((a)[2]), "r"((a)[3]), \
                   "r"(b0), "r"(b1))
#define MMA_F16(d, a, b0, b1) \
    asm volatile("mma.sync.aligned.m16n8k16.row.col.f32.f16.f16.f32 " \
                 "{%0,%1,%2,%3}, {%4,%5,%6,%7}, {%8,%9}, {%0,%1,%2,%3};" \
                 : "+f"((d)[0]), "+f"((d)[1]), "+f"((d)[2]), "+f"((d)[3]) \
                 : "r"((a)[0]), "r"((a)[1]), "r"((a)[2]), "r"((a)[3]), \
                   "r"(b0), "r"(b1))

#define CP_A16(dst, src) \
    asm volatile("cp.async.cg.shared.global [%0], [%1], 16;" \
                 :: "r"(dst), "l"(src) : "memory")
#define CP_COMMIT() asm volatile("cp.async.commit_group;" ::: "memory")
#define CP_WAIT(n)  asm volatile("cp.async.wait_group %0;" :: "n"(n) : "memory")

__device__ __forceinline__ uint32_t pack_bf16(float lo, float hi) {
    uint32_t u = (uint32_t)__bfloat16_as_ushort(__float2bfloat16(lo)) |
                 ((uint32_t)__bfloat16_as_ushort(__float2bfloat16(hi)) << 16);
    return u;
}

// ===========================================================================
// Fused split kernel (proven): all six tensors -> bf16 hi/lo, one launch.
// ===========================================================================
#define XN4 1048576
#define WN4 262144
#define SPLIT_TOTAL (3 * XN4 + 3 * WN4)

__global__ __launch_bounds__(256)
void split_all_kernel(const float4* __restrict__ q, const float4* __restrict__ k,
                      const float4* __restrict__ v, const float4* __restrict__ Wq,
                      const float4* __restrict__ Wk, const float4* __restrict__ Wv,
                      __nv_bfloat16* __restrict__ Xhi, __nv_bfloat16* __restrict__ Xlo,
                      __nv_bfloat16* __restrict__ Whi, __nv_bfloat16* __restrict__ Wlo)
{
    int i = blockIdx.x * 256 + threadIdx.x;
    if (i >= SPLIT_TOTAL) return;

    const float4* src;
    __nv_bfloat16 *hi, *lo;
    int idx;
    if (i < 3 * XN4) {
        int r = i / XN4;
        idx = i - r * XN4;
        src = (r == 0) ? q : (r == 1) ? k : v;
        hi = Xhi + (size_t)r * 4194304;
        lo = Xlo + (size_t)r * 4194304;
    } else {
        int j = i - 3 * XN4;
        int r = j / WN4;
        idx = j - r * WN4;
        src = (r == 0) ? Wq : (r == 1) ? Wk : Wv;
        hi = Whi + (size_t)r * 1048576;
        lo = Wlo + (size_t)r * 1048576;
    }

    float4 val = src[idx];
    float xs[4] = {val.x, val.y, val.z, val.w};
    uint32_t hb[4], lb[4];
#pragma unroll
    for (int j = 0; j < 4; j++) {
        __nv_bfloat16 h = __float2bfloat16(xs[j]);
        __nv_bfloat16 l = __float2bfloat16(xs[j] - __bfloat162float(h));
        hb[j] = (uint32_t)__bfloat16_as_ushort(h);
        lb[j] = (uint32_t)__bfloat16_as_ushort(l);
    }
    uint2 hp, lp;
    hp.x = hb[0] | (hb[1] << 16); hp.y = hb[2] | (hb[3] << 16);
    lp.x = lb[0] | (lb[1] << 16); lp.y = lb[2] | (lb[3] << 16);
    reinterpret_cast<uint2*>(hi)[idx] = hp;
    reinterpret_cast<uint2*>(lo)[idx] = lp;
}

// ===========================================================================
// Projection GEMM (exact 429us config): 512 threads, CTA tile 256x128,
// 16 warps (8m x 2n), warp tile 32x64, K-chunk 64, SW128, cp.async 2-stage.
// ===========================================================================
#define PROJ_STAGE  98304
#define PROJ_SMEM   (2 * PROJ_STAGE)
#define PROJ_NCHUNK (DMODEL / 64)   // 16

__global__ __launch_bounds__(512)
void proj_mma_kernel(const __nv_bfloat16* __restrict__ Xhi_all,
                     const __nv_bfloat16* __restrict__ Xlo_all,
                     const __nv_bfloat16* __restrict__ Whi_all,
                     const __nv_bfloat16* __restrict__ Wlo_all,
                     __nv_bfloat16* __restrict__ Qhi, __nv_bfloat16* __restrict__ Qlo,
                     __nv_bfloat16* __restrict__ Khi, __nv_bfloat16* __restrict__ Klo,
                     __half* __restrict__ Vh)
{
    extern __shared__ char smp[];
    const uint32_t sm0 = smem_u32(smp);

    const int tid  = threadIdx.x;
    const int wid  = tid >> 5, lane = tid & 31;
    const int wm   = wid >> 1;
    const int wn   = wid & 1;
    const int m0   = blockIdx.x * 256;
    const int n0   = blockIdx.y * 128;
    const int z    = blockIdx.z;

    const uint4* gAh = (const uint4*)(Xhi_all + (size_t)z * 4096 * 1024 + (size_t)m0 * 1024);
    const uint4* gAl = (const uint4*)(Xlo_all + (size_t)z * 4096 * 1024 + (size_t)m0 * 1024);
    const uint4* gBh = (const uint4*)(Whi_all + (size_t)z * 1024 * 1024 + (size_t)n0 * 1024);
    const uint4* gBl = (const uint4*)(Wlo_all + (size_t)z * 1024 * 1024 + (size_t)n0 * 1024);

    auto fill = [&](int c) {
        uint32_t sb = sm0 + (c & 1) * PROJ_STAGE;
#pragma unroll
        for (int i = 0; i < 12; i++) {
            int lin = tid + i * 512;
            int region = lin >> 11;          // 0:Ahi 1:Alo 2:B
            int rem = lin & 2047;
            const uint4* src;
            uint32_t dst;
            if (region < 2) {
                int row = rem >> 3, col = rem & 7;   // row 0..255
                src = (region == 0 ? gAh : gAl) + (size_t)row * 128 + c * 8 + col;
                dst = sb + region * 32768 + sw128(row * 128 + col * 16);
            } else {
                int sub = rem >> 10;                  // 0:Bhi 1:Blo
                int r2  = rem & 1023;
                int row = r2 >> 3, col = r2 & 7;      // row 0..127
                src = (sub == 0 ? gBh : gBl) + (size_t)row * 128 + c * 8 + col;
                dst = sb + 65536 + sub * 16384 + sw128(row * 128 + col * 16);
            }
            CP_A16(dst, src);
        }
    };

    float acc[2][8][4];
#pragma unroll
    for (int i = 0; i < 2; i++)
#pragma unroll
        for (int j = 0; j < 8; j++)
#pragma unroll
            for (int e = 0; e < 4; e++) acc[i][j][e] = 0.f;

    const int rIn    = lane & 7;
    const int a_rsel = ((lane >> 3) & 1) * 8;
    const int a_ksel = ((lane >> 4) & 1) * 16;
    const int b_nsel = ((lane >> 4) & 1) * 8;
    const int b_ksel = ((lane >> 3) & 1) * 16;

    fill(0);
    CP_COMMIT();

    for (int c = 0; c < PROJ_NCHUNK; c++) {
        if (c + 1 < PROJ_NCHUNK) {
            fill(c + 1);
            CP_COMMIT();
            CP_WAIT(1);
        } else {
            CP_WAIT(0);
        }
        __syncthreads();

        const uint32_t st = sm0 + (c & 1) * PROJ_STAGE;
        const uint32_t ah_u = st, al_u = st + 32768;
        const uint32_t bh_u = st + 65536, bl_u = st + 81920;

#pragma unroll
        for (int ks = 0; ks < 4; ks++) {
            uint32_t ah[2][4], al[2][4];
#pragma unroll
            for (int mi = 0; mi < 2; mi++) {
                int row = wm * 32 + mi * 16 + a_rsel + rIn;
                uint32_t off = sw128(row * 128 + ks * 32 + a_ksel);
                LDSM_X4(ah[mi][0], ah[mi][1], ah[mi][2], ah[mi][3], ah_u + off);
                LDSM_X4(al[mi][0], al[mi][1], al[mi][2], al[mi][3], al_u + off);
            }
#pragma unroll
            for (int njp = 0; njp < 4; njp++) {
                int nrow = wn * 64 + njp * 16 + b_nsel + rIn;
                uint32_t off = sw128(nrow * 128 + ks * 32 + b_ksel);
                uint32_t bhf[4], blf[4];
                LDSM_X4(bhf[0], bhf[1], bhf[2], bhf[3], bh_u + off);
                LDSM_X4(blf[0], blf[1], blf[2], blf[3], bl_u + off);
#pragma unroll
                for (int mi = 0; mi < 2; mi++) {
                    MMA_BF16(acc[mi][njp * 2],     ah[mi], bhf[0], bhf[1]);
                    MMA_BF16(acc[mi][njp * 2],     al[mi], bhf[0], bhf[1]);
                    MMA_BF16(acc[mi][njp * 2],     ah[mi], blf[0], blf[1]);
                    MMA_BF16(acc[mi][njp * 2 + 1], ah[mi], bhf[2], bhf[3]);
                    MMA_BF16(acc[mi][njp * 2 + 1], al[mi], bhf[2], bhf[3]);
                    MMA_BF16(acc[mi][njp * 2 + 1], ah[mi], blf[2], blf[3]);
                }
            }
        }
        __syncthreads();
    }

    // Epilogue: head-split [b][h][s][hd]; Q/K -> bf16 hi/lo, V -> fp16
    const int rr = lane >> 2;
    const int cc = (lane & 3) * 2;
    __nv_bfloat16* OutHi = (z == 0) ? Qhi : Khi;
    __nv_bfloat16* OutLo = (z == 0) ? Qlo : Klo;
#pragma unroll
    for (int mi = 0; mi < 2; mi++) {
#pragma unroll
        for (int nj = 0; nj < 8; nj++) {
            int n  = n0 + wn * 64 + nj * 8 + cc;
            int h  = n >> 6, hd = n & 63;
            int m  = m0 + wm * 32 + mi * 16 + rr;
            int bb = m >> 11, ss = m & 2047;
            size_t idx0 = (((size_t)(bb * NHEADS + h)) * SEQ + ss) * HDIM + hd;
#pragma unroll
            for (int half_i = 0; half_i < 2; half_i++) {   // rows m, m+8
                float v0 = acc[mi][nj][half_i * 2 + 0];
                float v1 = acc[mi][nj][half_i * 2 + 1];
                size_t idx = idx0 + (size_t)half_i * 8 * HDIM;
                if (z == 2) {
                    __half2 hv = __floats2half2_rn(v0, v1);
                    *reinterpret_cast<__half2*>(Vh + idx) = hv;
                } else {
                    __nv_bfloat16 h0 = __float2bfloat16(v0);
                    __nv_bfloat16 h1 = __float2bfloat16(v1);
                    uint32_t uhi = (uint32_t)__bfloat16_as_ushort(h0) |
                                   ((uint32_t)__bfloat16_as_ushort(h1) << 16);
                    uint32_t ulo = pack_bf16(v0 - __bfloat162float(h0),
                                             v1 - __bfloat162float(h1));
                    *reinterpret_cast<uint32_t*>(OutHi + idx) = uhi;
                    *reinterpret_cast<uint32_t*>(OutLo + idx) = ulo;
                }
            }
        }
    }
}

// ===========================================================================
// Tensor-core flash attention. Round 12: 4 warps x 32 q-rows (was 8 x 16).
// Each warp reads K/V once per tile -> LDSM traffic per tile halves.
// 128 threads, q-block 128, 2-stage KV. SMEM: Q 32KB | 2 x 24KB = 80KB.
// ===========================================================================
#define AT_SMEM (32768 + 2 * 24576)
#define NT      (SEQ / 64)

__global__ __launch_bounds__(128)
void attn_tc_kernel(const __nv_bfloat16* __restrict__ Qhi,
                    const __nv_bfloat16* __restrict__ Qlo,
                    const __nv_bfloat16* __restrict__ Khi,
                    const __nv_bfloat16* __restrict__ Klo,
                    const __half* __restrict__ Vh,
                    float* __restrict__ Out)
{
    extern __shared__ char sma[];
    const uint32_t sm0 = smem_u32(sma);
    const int tid  = threadIdx.x;
    const int lane = tid & 31;
    const int wq   = tid >> 5;           // 0..3 -> q-rows wq*32..+31
    const int q0   = blockIdx.x * 128;
    const int h    = blockIdx.y;
    const int b    = blockIdx.z;
    const size_t base = ((size_t)(b * NHEADS + h)) * SEQ * HDIM;

    const uint4* gqh = (const uint4*)(Qhi + base + (size_t)q0 * HDIM);
    const uint4* gql = (const uint4*)(Qlo + base + (size_t)q0 * HDIM);
    const uint4* gkh = (const uint4*)(Khi + base);
    const uint4* gkl = (const uint4*)(Klo + base);
    const uint4* gvh = (const uint4*)(Vh  + base);

    // ---- load Q tile (128 x 64 bf16, hi+lo) into smem: 1024 uint4 each
#pragma unroll
    for (int i = 0; i < 8; i++) {
        int lin = tid + i * 128;
        int row = lin >> 3, col = lin & 7;
        uint32_t off = sw128(row * 128 + col * 16);
        *reinterpret_cast<uint4*>(sma + off)         = gqh[row * 8 + col];
        *reinterpret_cast<uint4*>(sma + 16384 + off) = gql[row * 8 + col];
    }

    // K hi (8K) + K lo (8K) + V fp16 (8K) per stage: 1536 uint4 / 128 thr
    auto kv_fill = [&](uint32_t dstbase, int kt) {
#pragma unroll
        for (int i = 0; i < 12; i++) {
            int lin = tid + i * 128;
            int mat = lin >> 9;                 // 0: Khi, 1: Klo, 2: V
            int rem = lin & 511;
            int row = rem >> 3, col = rem & 7;
            const uint4* src =
                (mat == 0 ? gkh : mat == 1 ? gkl : gvh)
                + (size_t)(kt + row) * 8 + col;
            uint32_t dst = dstbase + mat * 8192 + sw128(row * 128 + col * 16);
            CP_A16(dst, src);
        }
    };
    kv_fill(sm0 + 32768, 0);
    CP_COMMIT();

    __syncthreads();   // Q smem ready

    const int rIn    = lane & 7;
    const int a_rsel = ((lane >> 3) & 1) * 8;
    const int a_ksel = ((lane >> 4) & 1) * 16;
    const int b_nsel = ((lane >> 4) & 1) * 8;
    const int b_ksel = ((lane >> 3) & 1) * 16;
    const int v_rsel = ((lane >> 3) & 1) * 8;
    const int v_nsel = ((lane >> 4) & 1) * 16;

    // Q fragments: 32 q-rows per warp (mi = 0,1 -> rows wq*32+mi*16..+15)
    uint32_t qh[4][2][4], ql[4][2][4];
#pragma unroll
    for (int ks = 0; ks < 4; ks++) {
#pragma unroll
        for (int mi = 0; mi < 2; mi++) {
            int row = wq * 32 + mi * 16 + a_rsel + rIn;
            uint32_t off = sw128(row * 128 + ks * 32 + a_ksel);
            LDSM_X4(qh[ks][mi][0], qh[ks][mi][1], qh[ks][mi][2], qh[ks][mi][3],
                    sm0 + off);
            LDSM_X4(ql[ks][mi][0], ql[ks][mi][1], ql[ks][mi][2], ql[ks][mi][3],
                    sm0 + 16384 + off);
        }
    }

    float o[2][8][4];
#pragma unroll
    for (int mi = 0; mi < 2; mi++)
#pragma unroll
        for (int v = 0; v < 8; v++)
#pragma unroll
            for (int e = 0; e < 4; e++) o[mi][v][e] = 0.f;
    float mrow[2][2] = {{-3.0e38f, -3.0e38f}, {-3.0e38f, -3.0e38f}};
    float lrow[2][2] = {{0.f, 0.f}, {0.f, 0.f}};

    for (int t = 0; t < NT; t++) {
        if (t + 1 < NT) {
            kv_fill(sm0 + 32768 + ((t + 1) & 1) * 24576, (t + 1) * 64);
            CP_COMMIT();
            CP_WAIT(1);
        } else {
            CP_WAIT(0);
        }
        __syncthreads();
        const uint32_t kb = sm0 + 32768 + (t & 1) * 24576;
        const uint32_t vb = kb + 16384;

        // ---- S = Q K^T (3-term bf16 split) for both 16-row halves
        float s[2][8][4];
#pragma unroll
        for (int mi = 0; mi < 2; mi++)
#pragma unroll
            for (int j = 0; j < 8; j++)
#pragma unroll
                for (int e = 0; e < 4; e++) s[mi][j][e] = 0.f;
#pragma unroll
        for (int ks = 0; ks < 4; ks++) {
#pragma unroll
            for (int np = 0; np < 4; np++) {
                uint32_t off = sw128((np * 16 + b_nsel + rIn) * 128 + ks * 32 + b_ksel);
                uint32_t kf[4], lf[4];
                LDSM_X4(kf[0], kf[1], kf[2], kf[3], kb + off);
                LDSM_X4(lf[0], lf[1], lf[2], lf[3], kb + 8192 + off);
#pragma unroll
                for (int mi = 0; mi < 2; mi++) {
                    MMA_BF16(s[mi][np * 2],     qh[ks][mi], kf[0], kf[1]);
                    MMA_BF16(s[mi][np * 2],     ql[ks][mi], kf[0], kf[1]);
                    MMA_BF16(s[mi][np * 2],     qh[ks][mi], lf[0], lf[1]);
                    MMA_BF16(s[mi][np * 2 + 1], qh[ks][mi], kf[2], kf[3]);
                    MMA_BF16(s[mi][np * 2 + 1], ql[ks][mi], kf[2], kf[3]);
                    MMA_BF16(s[mi][np * 2 + 1], qh[ks][mi], lf[2], lf[3]);
                }
            }
        }

        // ---- softmax (exp2 domain) + P fp16 fragments, per 16-row half
        uint32_t ap[2][4][4];
#pragma unroll
        for (int mi = 0; mi < 2; mi++) {
            float mt0 = -3.0e38f, mt1 = -3.0e38f;
#pragma unroll
            for (int j = 0; j < 8; j++) {
                mt0 = fmaxf(mt0, fmaxf(s[mi][j][0], s[mi][j][1]));
                mt1 = fmaxf(mt1, fmaxf(s[mi][j][2], s[mi][j][3]));
            }
            mt0 = fmaxf(mt0, __shfl_xor_sync(0xffffffffu, mt0, 1));
            mt0 = fmaxf(mt0, __shfl_xor_sync(0xffffffffu, mt0, 2));
            mt1 = fmaxf(mt1, __shfl_xor_sync(0xffffffffu, mt1, 1));
            mt1 = fmaxf(mt1, __shfl_xor_sync(0xffffffffu, mt1, 2));
            float M0 = fmaxf(mrow[mi][0], mt0 * EXP2_SCALE);
            float M1 = fmaxf(mrow[mi][1], mt1 * EXP2_SCALE);
            float a0 = ex2f(mrow[mi][0] - M0);
            float a1 = ex2f(mrow[mi][1] - M1);
            mrow[mi][0] = M0; mrow[mi][1] = M1;

            float rs0 = 0.f, rs1 = 0.f;
#pragma unroll
            for (int jp = 0; jp < 4; jp++) {
#pragma unroll
                for (int half_i = 0; half_i < 2; half_i++) {
                    int j = jp * 2 + half_i;
                    float p0 = ex2f(fmaf(s[mi][j][0], EXP2_SCALE, -M0));
                    float p1 = ex2f(fmaf(s[mi][j][1], EXP2_SCALE, -M0));
                    float p2 = ex2f(fmaf(s[mi][j][2], EXP2_SCALE, -M1));
                    float p3 = ex2f(fmaf(s[mi][j][3], EXP2_SCALE, -M1));
                    __half2 h01 = __floats2half2_rn(p0, p1);
                    __half2 h23 = __floats2half2_rn(p2, p3);
                    float2 f01 = __half22float2(h01);
                    float2 f23 = __half22float2(h23);
                    rs0 += f01.x + f01.y;
                    rs1 += f23.x + f23.y;
                    ap[mi][jp][half_i * 2 + 0] = *reinterpret_cast<uint32_t*>(&h01);
                    ap[mi][jp][half_i * 2 + 1] = *reinterpret_cast<uint32_t*>(&h23);
                }
            }
            rs0 += __shfl_xor_sync(0xffffffffu, rs0, 1);
            rs0 += __shfl_xor_sync(0xffffffffu, rs0, 2);
            rs1 += __shfl_xor_sync(0xffffffffu, rs1, 1);
            rs1 += __shfl_xor_sync(0xffffffffu, rs1, 2);
            lrow[mi][0] = lrow[mi][0] * a0 + rs0;
            lrow[mi][1] = lrow[mi][1] * a1 + rs1;
#pragma unroll
            for (int v = 0; v < 8; v++) {
                o[mi][v][0] *= a0; o[mi][v][1] *= a0;
                o[mi][v][2] *= a1; o[mi][v][3] *= a1;
            }
        }

        // ---- O += P V (single fp16 term), V read once per warp
#pragma unroll
        for (int t4 = 0; t4 < 4; t4++) {
#pragma unroll
            for (int vp = 0; vp < 4; vp++) {
                uint32_t off = sw128((t4 * 16 + v_rsel + rIn) * 128 + vp * 32 + v_nsel);
                uint32_t vf[4];
                LDSM_X4_T(vf[0], vf[1], vf[2], vf[3], vb + off);
#pragma unroll
                for (int mi = 0; mi < 2; mi++) {
                    MMA_F16(o[mi][vp * 2],     ap[mi][t4], vf[0], vf[1]);
                    MMA_F16(o[mi][vp * 2 + 1], ap[mi][t4], vf[2], vf[3]);
                }
            }
        }
        __syncthreads();   // all reads of this buffer done before refill
    }

    // ---- epilogue: normalize, write out[b][s][h*64+hd]
    int hd0 = h * 64 + 2 * (lane & 3);
#pragma unroll
    for (int mi = 0; mi < 2; mi++) {
        float inv0 = 1.f / lrow[mi][0];
        float inv1 = 1.f / lrow[mi][1];
        int s0 = q0 + wq * 32 + mi * 16 + (lane >> 2);
#pragma unroll
        for (int v = 0; v < 8; v++) {
            float2 w0 = make_float2(o[mi][v][0] * inv0, o[mi][v][1] * inv0);
            float2 w1 = make_float2(o[mi][v][2] * inv1, o[mi][v][3] * inv1);
            *reinterpret_cast<float2*>(
                &Out[(size_t)(b * SEQ + s0) * DMODEL + hd0 + v * 8]) = w0;
            *reinterpret_cast<float2*>(
                &Out[(size_t)(b * SEQ + s0 + 8) * DMODEL + hd0 + v * 8]) = w1;
        }
    }
}

// ---------------------------------------------------------------------------
extern "C" void kernel_launch(void* const* d_in, const int* in_sizes, int n_in,
                              void* d_out, int out_size)
{
    const float* q  = (const float*)d_in[0];
    const float* k  = (const float*)d_in[1];
    const float* v  = (const float*)d_in[2];
    const float* Wq = (const float*)d_in[3];
    const float* Wk = (const float*)d_in[4];
    const float* Wv = (const float*)d_in[5];
    float* out = (float*)d_out;

    __nv_bfloat16 *Xhi, *Xlo, *Whi, *Wlo;
    __nv_bfloat16 *Qhi, *Qlo, *Khi, *Klo;
    __half *Vh;
    cudaGetSymbolAddress((void**)&Xhi, g_Xhi);
    cudaGetSymbolAddress((void**)&Xlo, g_Xlo);
    cudaGetSymbolAddress((void**)&Whi, g_Whi);
    cudaGetSymbolAddress((void**)&Wlo, g_Wlo);
    cudaGetSymbolAddress((void**)&Qhi, g_Qhi);
    cudaGetSymbolAddress((void**)&Qlo, g_Qlo);
    cudaGetSymbolAddress((void**)&Khi, g_Khi);
    cudaGetSymbolAddress((void**)&Klo, g_Klo);
    cudaGetSymbolAddress((void**)&Vh,  g_Vh);

    cudaFuncSetAttribute(proj_mma_kernel,
                         cudaFuncAttributeMaxDynamicSharedMemorySize, PROJ_SMEM);
    cudaFuncSetAttribute(attn_tc_kernel,
                         cudaFuncAttributeMaxDynamicSharedMemorySize, AT_SMEM);

    split_all_kernel<<<(SPLIT_TOTAL + 255) / 256, 256>>>(
        (const float4*)q, (const float4*)k, (const float4*)v,
        (const float4*)Wq, (const float4*)Wk, (const float4*)Wv,
        Xhi, Xlo, Whi, Wlo);

    dim3 pg(4096 / 256, 1024 / 128, 3);   // (16, 8, 3)
    proj_mma_kernel<<<pg, 512, PROJ_SMEM>>>(Xhi, Xlo, Whi, Wlo,
                                            Qhi, Qlo, Khi, Klo, Vh);

    dim3 ag(SEQ / 128, NHEADS, BATCH);    // (16, 16, 2)
    attn_tc_kernel<<<ag, 128, AT_SMEM>>>(Qhi, Qlo, Khi, Klo, Vh, out);
}